// round 9
// baseline (speedup 1.0000x reference)
#include <cuda_runtime.h>

// DynamicMaskHead fused kernel for GB300 (sm_103a), round 9.
// R8 (61.6us) analysis: fma-busy == FFMA2 floor (28.7us); L1/LDS 65.6% is the
// co-bottleneck because weights reload every 2-pixel iter. R9: NT=192 at
// 3 CTA/SM raises the reg cap to 113 -> 4-pixel tiles (acc 64 regs), halving
// LDS per head-pixel. Grid stays 400 blocks = one wave.

#define WW   160
#define OW   320
#define HW   15360
#define NP   169
#define NT   192

// weight-pair layout (u64 indices in swp):
//   [0,80)    l0wT: input-major, i*8 + c
//   [80,88)   l0b
//   [88,152)  l1w:  c*8 + i
//   [152,160) l1b
//   [160,168) l2w (pre-scaled 0.5)
//   [168]     l2b (pre-scaled 0.5)
#define SWPAIRS 169
#define TILE_PAIRS (49 * WW)
#define SMEM_BYTES ((TILE_PAIRS + SWPAIRS + 1) * 8)

typedef unsigned long long u64;

__device__ __forceinline__ u64 pk(float lo, float hi) {
    u64 r; asm("mov.b64 %0, {%1, %2};" : "=l"(r) : "f"(lo), "f"(hi)); return r;
}
__device__ __forceinline__ u64 dup(float v) {
    u64 r; asm("mov.b64 %0, {%1, %1};" : "=l"(r) : "f"(v)); return r;
}
__device__ __forceinline__ void upk(u64 v, float& lo, float& hi) {
    asm("mov.b64 {%0, %1}, %2;" : "=f"(lo), "=f"(hi) : "l"(v));
}
__device__ __forceinline__ u64 ffma2(u64 a, u64 b, u64 c) {
    u64 d; asm("fma.rn.f32x2 %0, %1, %2, %3;" : "=l"(d) : "l"(a), "l"(b), "l"(c)); return d;
}
__device__ __forceinline__ u64 add2(u64 a, u64 b) {
    u64 d; asm("add.rn.f32x2 %0, %1, %2;" : "=l"(d) : "l"(a), "l"(b)); return d;
}
__device__ __forceinline__ u64 mul2(u64 a, u64 b) {
    u64 d; asm("mul.rn.f32x2 %0, %1, %2;" : "=l"(d) : "l"(a), "l"(b)); return d;
}
__device__ __forceinline__ u64 relu2(u64 v) {
    float lo, hi; upk(v, lo, hi);
    return pk(fmaxf(lo, 0.0f), fmaxf(hi, 0.0f));
}
// x = 0.5*logit: sigmoid(L) = 0.5*tanh(0.5L) + 0.5
__device__ __forceinline__ float sig_h(float x) {
    float t;
    asm("tanh.approx.f32 %0, %1;" : "=f"(t) : "f"(x));
    return fmaf(0.5f, t, 0.5f);
}

__global__ __launch_bounds__(NT, 3)
void dmh_kernel(const float* __restrict__ feats,     // [2, 8, 96, 160]
                const float* __restrict__ p1,        // [N, 169]
                const float* __restrict__ p2,        // [N, 169]
                const float* __restrict__ loc,       // [N, 2]
                const float* __restrict__ off,       // [N, 2]
                const int*   __restrict__ imi,       // [N]
                const int*   __restrict__ fpn,       // [N]
                float*       __restrict__ out)       // [2, N, 192, 320]
{
    extern __shared__ u64 smem_u64[];
    u64* sLp = smem_u64;                       // [TILE_PAIRS] packed half-logits
    u64* swp = smem_u64 + TILE_PAIRS;          // [SWPAIRS] weight pairs

    const int tid    = threadIdx.x;
    const int inst   = blockIdx.x;
    const int slab   = blockIdx.y;             // 0 or 1
    const int n_inst = gridDim.x;

    // ---- Repack: interleave head0/head1 weights into pairs ----
    if (tid < NP) {
        float w1 = p1[inst * NP + tid];
        float w2 = p2[inst * NP + tid];
        int d;
        if      (tid < 80)  { const int c = tid / 10; d = (tid - c * 10) * 8 + c; }  // l0 transposed
        else if (tid < 144) { d = 88 + (tid - 80); }
        else if (tid < 152) { d = 160 + (tid - 144); w1 *= 0.5f; w2 *= 0.5f; }
        else if (tid < 160) { d = 80 + (tid - 152); }
        else if (tid < 168) { d = 152 + (tid - 160); }
        else                { d = 168; w1 *= 0.5f; w2 *= 0.5f; }
        swp[d] = pk(w1, w2);
    }

    const int   lvl     = fpn[inst];
    const float inv_soi = 1.0f / (64.0f * (float)(1 << lvl));
    const float lx0 = loc[2 * inst + 0];
    const float ly0 = loc[2 * inst + 1];
    const float lx1 = lx0 + off[2 * inst + 0] * 128.0f;
    const float ly1 = ly0 + off[2 * inst + 1] * 128.0f;
    const float* fb = feats + (size_t)imi[inst] * (8 * HW);
    const float dxs = -8.0f * inv_soi;
    __syncthreads();

    // ---------------- Phase 1: packed MLP, 4 px x 2 heads per iter ----------
    const int ybase = slab ? 47 : 0;
    const int nrows = 48 + slab;               // 48 or 49
    const int ng    = nrows * (WW / 4);        // 4-px groups

    #pragma unroll 1
    for (int g = tid; g < ng; g += NT) {
        const int rowl = g / (WW / 4);
        const int px   = (g - rowl * (WW / 4)) * 4;
        const int y    = ybase + rowl;
        const int base = y * WW + px;

        // coordinate pairs {head0, head1} for the 4 pixels
        const float yc = (float)(y * 8 + 4);
        const float xc = (float)(px * 8 + 4);
        const u64 yp = pk((ly0 - yc) * inv_soi, (ly1 - yc) * inv_soi);
        u64 xp0 = pk((lx0 - xc) * inv_soi, (lx1 - xc) * inv_soi);
        const u64 dd = dup(dxs);
        u64 xp1 = add2(xp0, dd);
        u64 xp2 = add2(xp1, dd);
        u64 xp3 = add2(xp2, dd);

        // layer-0 accumulators: 4 px x 8 ch packed pairs (bias init)
        u64 a[4][8];
        {
            const ulonglong2* bp = reinterpret_cast<const ulonglong2*>(swp + 80);
            const ulonglong2 b0 = bp[0], b1 = bp[1], b2 = bp[2], b3 = bp[3];
            #pragma unroll
            for (int k = 0; k < 4; ++k) {
                a[k][0] = b0.x; a[k][1] = b0.y; a[k][2] = b1.x; a[k][3] = b1.y;
                a[k][4] = b2.x; a[k][5] = b2.y; a[k][6] = b3.x; a[k][7] = b3.y;
            }
        }

        // apply one input (per-pixel operand x0..x3) with weights for input I
        #define L0STEP(I, X0, X1, X2, X3)                                     \
        {                                                                     \
            const ulonglong2* Wp = reinterpret_cast<const ulonglong2*>(swp + (I) * 8); \
            const ulonglong2 wa = Wp[0], wb = Wp[1], wc = Wp[2], wd = Wp[3];  \
            a[0][0] = ffma2(X0, wa.x, a[0][0]); a[1][0] = ffma2(X1, wa.x, a[1][0]); \
            a[2][0] = ffma2(X2, wa.x, a[2][0]); a[3][0] = ffma2(X3, wa.x, a[3][0]); \
            a[0][1] = ffma2(X0, wa.y, a[0][1]); a[1][1] = ffma2(X1, wa.y, a[1][1]); \
            a[2][1] = ffma2(X2, wa.y, a[2][1]); a[3][1] = ffma2(X3, wa.y, a[3][1]); \
            a[0][2] = ffma2(X0, wb.x, a[0][2]); a[1][2] = ffma2(X1, wb.x, a[1][2]); \
            a[2][2] = ffma2(X2, wb.x, a[2][2]); a[3][2] = ffma2(X3, wb.x, a[3][2]); \
            a[0][3] = ffma2(X0, wb.y, a[0][3]); a[1][3] = ffma2(X1, wb.y, a[1][3]); \
            a[2][3] = ffma2(X2, wb.y, a[2][3]); a[3][3] = ffma2(X3, wb.y, a[3][3]); \
            a[0][4] = ffma2(X0, wc.x, a[0][4]); a[1][4] = ffma2(X1, wc.x, a[1][4]); \
            a[2][4] = ffma2(X2, wc.x, a[2][4]); a[3][4] = ffma2(X3, wc.x, a[3][4]); \
            a[0][5] = ffma2(X0, wc.y, a[0][5]); a[1][5] = ffma2(X1, wc.y, a[1][5]); \
            a[2][5] = ffma2(X2, wc.y, a[2][5]); a[3][5] = ffma2(X3, wc.y, a[3][5]); \
            a[0][6] = ffma2(X0, wd.x, a[0][6]); a[1][6] = ffma2(X1, wd.x, a[1][6]); \
            a[2][6] = ffma2(X2, wd.x, a[2][6]); a[3][6] = ffma2(X3, wd.x, a[3][6]); \
            a[0][7] = ffma2(X0, wd.y, a[0][7]); a[1][7] = ffma2(X1, wd.y, a[1][7]); \
            a[2][7] = ffma2(X2, wd.y, a[2][7]); a[3][7] = ffma2(X3, wd.y, a[3][7]); \
        }

        L0STEP(0, xp0, xp1, xp2, xp3)
        L0STEP(1, yp,  yp,  yp,  yp)

        // features in two half-groups of 4 channels (bounds live regs)
        #pragma unroll
        for (int h = 0; h < 2; ++h) {
            float4 f0 = *reinterpret_cast<const float4*>(fb + (4 * h + 0) * HW + base);
            float4 f1 = *reinterpret_cast<const float4*>(fb + (4 * h + 1) * HW + base);
            float4 f2 = *reinterpret_cast<const float4*>(fb + (4 * h + 2) * HW + base);
            float4 f3 = *reinterpret_cast<const float4*>(fb + (4 * h + 3) * HW + base);
            #define FEED(J, F)                                                \
            {                                                                 \
                const u64 d0 = dup(F.x), d1 = dup(F.y);                       \
                const u64 d2 = dup(F.z), d3 = dup(F.w);                       \
                L0STEP(2 + 4 * h + (J), d0, d1, d2, d3)                       \
            }
            FEED(0, f0) FEED(1, f1) FEED(2, f2) FEED(3, f3)
            #undef FEED
        }
        #undef L0STEP

        #pragma unroll
        for (int k = 0; k < 4; ++k)
            #pragma unroll
            for (int c = 0; c < 8; ++c)
                a[k][c] = relu2(a[k][c]);

        // layer 1 channel-outer, layer 2 streamed into o[4]
        u64 o[4];
        { const u64 b2 = swp[168]; o[0] = b2; o[1] = b2; o[2] = b2; o[3] = b2; }
        #pragma unroll
        for (int c = 0; c < 8; ++c) {
            const ulonglong2* Wp = reinterpret_cast<const ulonglong2*>(swp + 88 + c * 8);
            const ulonglong2 wa = Wp[0], wb = Wp[1], wc = Wp[2], wd = Wp[3];
            const u64 bias = swp[152 + c];
            u64 t0 = ffma2(a[0][0], wa.x, bias);
            u64 t1 = ffma2(a[1][0], wa.x, bias);
            u64 t2 = ffma2(a[2][0], wa.x, bias);
            u64 t3 = ffma2(a[3][0], wa.x, bias);
            t0 = ffma2(a[0][1], wa.y, t0); t1 = ffma2(a[1][1], wa.y, t1);
            t2 = ffma2(a[2][1], wa.y, t2); t3 = ffma2(a[3][1], wa.y, t3);
            t0 = ffma2(a[0][2], wb.x, t0); t1 = ffma2(a[1][2], wb.x, t1);
            t2 = ffma2(a[2][2], wb.x, t2); t3 = ffma2(a[3][2], wb.x, t3);
            t0 = ffma2(a[0][3], wb.y, t0); t1 = ffma2(a[1][3], wb.y, t1);
            t2 = ffma2(a[2][3], wb.y, t2); t3 = ffma2(a[3][3], wb.y, t3);
            t0 = ffma2(a[0][4], wc.x, t0); t1 = ffma2(a[1][4], wc.x, t1);
            t2 = ffma2(a[2][4], wc.x, t2); t3 = ffma2(a[3][4], wc.x, t3);
            t0 = ffma2(a[0][5], wc.y, t0); t1 = ffma2(a[1][5], wc.y, t1);
            t2 = ffma2(a[2][5], wc.y, t2); t3 = ffma2(a[3][5], wc.y, t3);
            t0 = ffma2(a[0][6], wd.x, t0); t1 = ffma2(a[1][6], wd.x, t1);
            t2 = ffma2(a[2][6], wd.x, t2); t3 = ffma2(a[3][6], wd.x, t3);
            t0 = ffma2(a[0][7], wd.y, t0); t1 = ffma2(a[1][7], wd.y, t1);
            t2 = ffma2(a[2][7], wd.y, t2); t3 = ffma2(a[3][7], wd.y, t3);
            const u64 w2 = swp[160 + c];
            o[0] = ffma2(relu2(t0), w2, o[0]);
            o[1] = ffma2(relu2(t1), w2, o[1]);
            o[2] = ffma2(relu2(t2), w2, o[2]);
            o[3] = ffma2(relu2(t3), w2, o[3]);
        }

        // packed half-logit pairs, 2 x STS.128
        u64* dst = sLp + rowl * WW + px;
        *reinterpret_cast<ulonglong2*>(dst)     = make_ulonglong2(o[0], o[1]);
        *reinterpret_cast<ulonglong2*>(dst + 2) = make_ulonglong2(o[2], o[3]);
    }
    __syncthreads();

    // ---------------- Phase 2: packed bilinear x2 + sigmoid ------------------
    // S_i = P[rA][i] + P[rB][i]  (rA==rB for odd rows -> S = 2P)
    //   col 4g: 0.25*(S_{cm1}+S_{c0})   4g+1: 0.5*S_{c0}
    //   4g+2:   0.25*(S_{c0}+S_{c1})    4g+3: 0.5*S_{c1}
    const u64 H = dup(0.5f);
    const u64 Q = dup(0.25f);
    float* ob0 = out + (size_t)inst * (192 * OW);
    float* ob1 = out + ((size_t)n_inst + inst) * (192 * OW);

    #pragma unroll 1
    for (int it = 0; it < 40; ++it) {
        const int q   = tid + it * NT;          // [0, 7680)
        const int oyl = q / 80;                 // 0..95
        const int g   = q - oyl * 80;           // 0..79
        const int oy  = slab * 96 + oyl;

        const int r1  = oy >> 1;
        const int rA  = (oy & 1) ? r1 : ((r1 > 0) ? r1 - 1 : 0);
        const u64* RB = sLp + (r1 - ybase) * WW;
        const u64* RA = sLp + (rA - ybase) * WW;

        const int c0  = 2 * g;
        const int cm1 = (g > 0) ? c0 - 1 : c0;

        const u64 Sm = add2(RA[cm1],    RB[cm1]);
        const u64 S0 = add2(RA[c0],     RB[c0]);
        const u64 S1 = add2(RA[c0 + 1], RB[c0 + 1]);

        const u64 e0 = mul2(add2(Sm, S0), Q);
        const u64 e1 = mul2(S0, H);
        const u64 e2 = mul2(add2(S0, S1), Q);
        const u64 e3 = mul2(S1, H);

        float a0, b0, a1, b1, a2, b2, a3, b3;
        upk(e0, a0, b0); upk(e1, a1, b1); upk(e2, a2, b2); upk(e3, a3, b3);

        float4 v0, v1;
        v0.x = sig_h(a0); v0.y = sig_h(a1); v0.z = sig_h(a2); v0.w = sig_h(a3);
        v1.x = sig_h(b0); v1.y = sig_h(b1); v1.z = sig_h(b2); v1.w = sig_h(b3);

        const int o = oy * OW + 4 * g;
        *reinterpret_cast<float4*>(ob0 + o) = v0;
        *reinterpret_cast<float4*>(ob1 + o) = v1;
    }
}

extern "C" void kernel_launch(void* const* d_in, const int* in_sizes, int n_in,
                              void* d_out, int out_size)
{
    const float* feats = (const float*)d_in[0];
    const float* p1    = (const float*)d_in[1];
    const float* p2    = (const float*)d_in[2];
    const float* loc   = (const float*)d_in[3];
    const float* off   = (const float*)d_in[4];
    const int*   imi   = (const int*)  d_in[5];
    const int*   fpn   = (const int*)  d_in[6];
    float* out = (float*)d_out;

    const int n_inst = in_sizes[5];   // 200

    static bool attr_set = false;
    if (!attr_set) {
        cudaFuncSetAttribute(dmh_kernel,
                             cudaFuncAttributeMaxDynamicSharedMemorySize,
                             (int)SMEM_BYTES);
        attr_set = true;
    }

    dim3 grid(n_inst, 2);             // 400 blocks (inst x slab), one wave @3 CTA/SM
    dmh_kernel<<<grid, NT, SMEM_BYTES>>>(feats, p1, p2, loc, off, imi, fpn, out);
}

// round 10
// speedup vs baseline: 1.2500x; 1.2500x over previous
#include <cuda_runtime.h>

// DynamicMaskHead fused kernel for GB300 (sm_103a), round 10.
// R8 body (61.6us: heads packed in f32x2, 2px/iter, 24 warps/SM) unchanged.
// Single structural change: wave fill. R8 ran 400 blocks on 444 slots (90%).
// R10: NT=192 @ 4 CTA/SM, 3 row-slabs -> 600 blocks on 592 slots (~100% fill,
// asynchronous retirement tail ~ one small block). Warps/SM stays 24.

#define WW   160
#define OW   320
#define HW   15360
#define NP   169
#define NT   192

// weight-pair layout (u64 indices in swp):
//   [0,80)    l0wT: input-major, i*8 + c
//   [80,88)   l0b
//   [88,152)  l1w:  c*8 + i
//   [152,160) l1b
//   [160,168) l2w (pre-scaled 0.5)
//   [168]     l2b (pre-scaled 0.5)
#define SWPAIRS 169
#define TILE_PAIRS (33 * WW)                 // 33 rows max per slab
#define SMEM_BYTES ((TILE_PAIRS + SWPAIRS + 1) * 8)

typedef unsigned long long u64;

__device__ __forceinline__ u64 pk(float lo, float hi) {
    u64 r; asm("mov.b64 %0, {%1, %2};" : "=l"(r) : "f"(lo), "f"(hi)); return r;
}
__device__ __forceinline__ u64 dup(float v) {
    u64 r; asm("mov.b64 %0, {%1, %1};" : "=l"(r) : "f"(v)); return r;
}
__device__ __forceinline__ void upk(u64 v, float& lo, float& hi) {
    asm("mov.b64 {%0, %1}, %2;" : "=f"(lo), "=f"(hi) : "l"(v));
}
__device__ __forceinline__ u64 ffma2(u64 a, u64 b, u64 c) {
    u64 d; asm("fma.rn.f32x2 %0, %1, %2, %3;" : "=l"(d) : "l"(a), "l"(b), "l"(c)); return d;
}
__device__ __forceinline__ u64 add2(u64 a, u64 b) {
    u64 d; asm("add.rn.f32x2 %0, %1, %2;" : "=l"(d) : "l"(a), "l"(b)); return d;
}
__device__ __forceinline__ u64 mul2(u64 a, u64 b) {
    u64 d; asm("mul.rn.f32x2 %0, %1, %2;" : "=l"(d) : "l"(a), "l"(b)); return d;
}
__device__ __forceinline__ u64 relu2(u64 v) {
    float lo, hi; upk(v, lo, hi);
    return pk(fmaxf(lo, 0.0f), fmaxf(hi, 0.0f));
}
// x = 0.5*logit: sigmoid(L) = 0.5*tanh(0.5L) + 0.5
__device__ __forceinline__ float sig_h(float x) {
    float t;
    asm("tanh.approx.f32 %0, %1;" : "=f"(t) : "f"(x));
    return fmaf(0.5f, t, 0.5f);
}

__global__ __launch_bounds__(NT, 4)
void dmh_kernel(const float* __restrict__ feats,     // [2, 8, 96, 160]
                const float* __restrict__ p1,        // [N, 169]
                const float* __restrict__ p2,        // [N, 169]
                const float* __restrict__ loc,       // [N, 2]
                const float* __restrict__ off,       // [N, 2]
                const int*   __restrict__ imi,       // [N]
                const int*   __restrict__ fpn,       // [N]
                float*       __restrict__ out)       // [2, N, 192, 320]
{
    extern __shared__ u64 smem_u64[];
    u64* sLp = smem_u64;                       // [TILE_PAIRS] packed half-logits
    u64* swp = smem_u64 + TILE_PAIRS;          // [SWPAIRS] weight pairs

    const int tid    = threadIdx.x;
    const int inst   = blockIdx.x;
    const int slab   = blockIdx.y;             // 0, 1, 2
    const int n_inst = gridDim.x;

    // ---- Repack: interleave head0/head1 weights into pairs ----
    if (tid < NP) {
        float w1 = p1[inst * NP + tid];
        float w2 = p2[inst * NP + tid];
        int d;
        if      (tid < 80)  { const int c = tid / 10; d = (tid - c * 10) * 8 + c; }  // l0 transposed
        else if (tid < 144) { d = 88 + (tid - 80); }
        else if (tid < 152) { d = 160 + (tid - 144); w1 *= 0.5f; w2 *= 0.5f; }
        else if (tid < 160) { d = 80 + (tid - 152); }
        else if (tid < 168) { d = 152 + (tid - 160); }
        else                { d = 168; w1 *= 0.5f; w2 *= 0.5f; }
        swp[d] = pk(w1, w2);
    }

    const int   lvl     = fpn[inst];
    const float inv_soi = 1.0f / (64.0f * (float)(1 << lvl));
    const float lx0 = loc[2 * inst + 0];
    const float ly0 = loc[2 * inst + 1];
    const float lx1 = lx0 + off[2 * inst + 0] * 128.0f;
    const float ly1 = ly0 + off[2 * inst + 1] * 128.0f;
    const float* fb = feats + (size_t)imi[inst] * (8 * HW);
    const float dxs = -8.0f * inv_soi;
    __syncthreads();

    // ---------------- Phase 1: packed MLP, 2 px x 2 heads per iter ----------
    // slab s produces output rows [64s, 64s+64) -> needs input rows
    // [32s - (s>0), 32s + 32)
    const int ybase = 32 * slab - (slab ? 1 : 0);
    const int nrows = 32 + (slab ? 1 : 0);     // 32 or 33
    const int npx   = nrows * WW;

    #pragma unroll 1
    for (int p = 2 * tid; p < npx; p += 2 * NT) {
        const int rowl = p / WW;
        const int px   = p - rowl * WW;          // even
        const int y    = ybase + rowl;
        const int base = y * WW + px;

        // coordinate pairs {head0, head1}
        const float yc = (float)(y * 8 + 4);
        const float xc = (float)(px * 8 + 4);
        const u64 yp  = pk((ly0 - yc) * inv_soi, (ly1 - yc) * inv_soi);
        const u64 xpA = pk((lx0 - xc) * inv_soi, (lx1 - xc) * inv_soi);
        const u64 xpB = add2(xpA, dup(dxs));

        // features for the 2 pixels (8 x LDG.64)
        float2 f2[8];
        #pragma unroll
        for (int j = 0; j < 8; ++j)
            f2[j] = *reinterpret_cast<const float2*>(fb + j * HW + base);

        // layer-0 accumulators: bias pairs
        u64 a0[8], a1[8];
        {
            const ulonglong2* bp = reinterpret_cast<const ulonglong2*>(swp + 80);
            #pragma unroll
            for (int h = 0; h < 4; ++h) {
                const ulonglong2 b = bp[h];
                a0[2 * h] = b.x; a0[2 * h + 1] = b.y;
                a1[2 * h] = b.x; a1[2 * h + 1] = b.y;
            }
        }

        // layer 0, input-outer over transposed weights
        #define L0STEP(I, XA, XB)                                             \
        {                                                                     \
            const ulonglong2* Wp = reinterpret_cast<const ulonglong2*>(swp + (I) * 8); \
            const ulonglong2 wa = Wp[0], wb = Wp[1], wc = Wp[2], wd = Wp[3];  \
            a0[0] = ffma2(XA, wa.x, a0[0]);  a1[0] = ffma2(XB, wa.x, a1[0]);  \
            a0[1] = ffma2(XA, wa.y, a0[1]);  a1[1] = ffma2(XB, wa.y, a1[1]);  \
            a0[2] = ffma2(XA, wb.x, a0[2]);  a1[2] = ffma2(XB, wb.x, a1[2]);  \
            a0[3] = ffma2(XA, wb.y, a0[3]);  a1[3] = ffma2(XB, wb.y, a1[3]);  \
            a0[4] = ffma2(XA, wc.x, a0[4]);  a1[4] = ffma2(XB, wc.x, a1[4]);  \
            a0[5] = ffma2(XA, wc.y, a0[5]);  a1[5] = ffma2(XB, wc.y, a1[5]);  \
            a0[6] = ffma2(XA, wd.x, a0[6]);  a1[6] = ffma2(XB, wd.x, a1[6]);  \
            a0[7] = ffma2(XA, wd.y, a0[7]);  a1[7] = ffma2(XB, wd.y, a1[7]);  \
        }
        L0STEP(0, xpA, xpB)
        L0STEP(1, yp,  yp)
        #pragma unroll
        for (int j = 0; j < 8; ++j) {
            const u64 fd0 = dup(f2[j].x);
            const u64 fd1 = dup(f2[j].y);
            L0STEP(2 + j, fd0, fd1)
        }
        #undef L0STEP

        #pragma unroll
        for (int c = 0; c < 8; ++c) { a0[c] = relu2(a0[c]); a1[c] = relu2(a1[c]); }

        // layer 1 channel-outer, layer 2 streamed into o
        u64 o0 = swp[168], o1 = o0;
        #pragma unroll
        for (int c = 0; c < 8; ++c) {
            const ulonglong2* Wp = reinterpret_cast<const ulonglong2*>(swp + 88 + c * 8);
            const ulonglong2 wa = Wp[0], wb = Wp[1], wc = Wp[2], wd = Wp[3];
            const u64 bias = swp[152 + c];
            u64 b0 = ffma2(a0[0], wa.x, bias);
            u64 b1 = ffma2(a1[0], wa.x, bias);
            b0 = ffma2(a0[1], wa.y, b0);  b1 = ffma2(a1[1], wa.y, b1);
            b0 = ffma2(a0[2], wb.x, b0);  b1 = ffma2(a1[2], wb.x, b1);
            b0 = ffma2(a0[3], wb.y, b0);  b1 = ffma2(a1[3], wb.y, b1);
            b0 = ffma2(a0[4], wc.x, b0);  b1 = ffma2(a1[4], wc.x, b1);
            b0 = ffma2(a0[5], wc.y, b0);  b1 = ffma2(a1[5], wc.y, b1);
            b0 = ffma2(a0[6], wd.x, b0);  b1 = ffma2(a1[6], wd.x, b1);
            b0 = ffma2(a0[7], wd.y, b0);  b1 = ffma2(a1[7], wd.y, b1);
            const u64 w2 = swp[160 + c];
            o0 = ffma2(relu2(b0), w2, o0);
            o1 = ffma2(relu2(b1), w2, o1);
        }

        sLp[rowl * WW + px]     = o0;    // packed {h0, h1} half-logits
        sLp[rowl * WW + px + 1] = o1;
    }
    __syncthreads();

    // ---------------- Phase 2: packed bilinear x2 + sigmoid ------------------
    // S_i = P[rA][i] + P[rB][i]  (rA==rB for odd rows -> S = 2P)
    //   col 4g: 0.25*(S_{cm1}+S_{c0})   4g+1: 0.5*S_{c0}
    //   4g+2:   0.25*(S_{c0}+S_{c1})    4g+3: 0.5*S_{c1}
    const u64 H = dup(0.5f);
    const u64 Q = dup(0.25f);
    float* ob0 = out + (size_t)inst * (192 * OW);
    float* ob1 = out + ((size_t)n_inst + inst) * (192 * OW);

    // 64 output rows x 80 quad-groups = 5120 work items; 27 guarded iters
    #pragma unroll 1
    for (int it = 0; it < 27; ++it) {
        const int q = tid + it * NT;
        if (q >= 64 * 80) break;
        const int oyl = q / 80;                 // 0..63
        const int g   = q - oyl * 80;           // 0..79
        const int oy  = 64 * slab + oyl;

        const int r1  = oy >> 1;
        const int rA  = (oy & 1) ? r1 : ((r1 > 0) ? r1 - 1 : 0);
        const u64* RB = sLp + (r1 - ybase) * WW;
        const u64* RA = sLp + (rA - ybase) * WW;

        const int c0  = 2 * g;
        const int cm1 = (g > 0) ? c0 - 1 : c0;

        const u64 Sm = add2(RA[cm1],    RB[cm1]);
        const u64 S0 = add2(RA[c0],     RB[c0]);
        const u64 S1 = add2(RA[c0 + 1], RB[c0 + 1]);

        const u64 e0 = mul2(add2(Sm, S0), Q);
        const u64 e1 = mul2(S0, H);
        const u64 e2 = mul2(add2(S0, S1), Q);
        const u64 e3 = mul2(S1, H);

        float a0, b0, a1, b1, a2, b2, a3, b3;
        upk(e0, a0, b0); upk(e1, a1, b1); upk(e2, a2, b2); upk(e3, a3, b3);

        float4 v0, v1;
        v0.x = sig_h(a0); v0.y = sig_h(a1); v0.z = sig_h(a2); v0.w = sig_h(a3);
        v1.x = sig_h(b0); v1.y = sig_h(b1); v1.z = sig_h(b2); v1.w = sig_h(b3);

        const int o = oy * OW + 4 * g;
        *reinterpret_cast<float4*>(ob0 + o) = v0;
        *reinterpret_cast<float4*>(ob1 + o) = v1;
    }
}

extern "C" void kernel_launch(void* const* d_in, const int* in_sizes, int n_in,
                              void* d_out, int out_size)
{
    const float* feats = (const float*)d_in[0];
    const float* p1    = (const float*)d_in[1];
    const float* p2    = (const float*)d_in[2];
    const float* loc   = (const float*)d_in[3];
    const float* off   = (const float*)d_in[4];
    const int*   imi   = (const int*)  d_in[5];
    const int*   fpn   = (const int*)  d_in[6];
    float* out = (float*)d_out;

    const int n_inst = in_sizes[5];   // 200

    static bool attr_set = false;
    if (!attr_set) {
        cudaFuncSetAttribute(dmh_kernel,
                             cudaFuncAttributeMaxDynamicSharedMemorySize,
                             (int)SMEM_BYTES);
        attr_set = true;
    }

    dim3 grid(n_inst, 3);             // 600 blocks on 592 slots @4 CTA/SM
    dmh_kernel<<<grid, NT, SMEM_BYTES>>>(feats, p1, p2, loc, off, imi, fpn, out);
}

// round 11
// speedup vs baseline: 1.3043x; 1.0435x over previous
#include <cuda_runtime.h>

// DynamicMaskHead fused kernel for GB300 (sm_103a), round 11.
// R10 (56.1us) body kept: heads packed in f32x2, 2px/iter, NT=192 @ 4 CTA/SM.
// R11 changes (targets: L1 72.8% busy + 600-on-592 tail):
//  - layer-1 {bias, w2} packed into one ulonglong2 -> saves 8 LDS.64/iter
//  - phase 2 row loads vectorized: LDS.128 for {S0,S1} pairs
//  - 6 slabs of 16 rows -> 1200 blocks ~ 2 waves of half-size blocks
//    (smooth asynchronous retirement; ragged edge halves)

#define WW   160
#define OW   320
#define HW   15360
#define NP   169
#define NT   192

// weight-pair layout (u64 indices in swp):
//   [0,80)    l0wT: input-major, i*8 + c
//   [80,88)   l0b
//   [88,168)  l1 blocks: c*10 + {0..7: w, 8: bias, 9: w2(pre-scaled 0.5)}
//   [168]     l2b (pre-scaled 0.5)
#define SWPAIRS 169
#define TILE_PAIRS (17 * WW)                 // 17 rows max per slab
#define SMEM_BYTES ((TILE_PAIRS + SWPAIRS + 1) * 8)

typedef unsigned long long u64;

__device__ __forceinline__ u64 pk(float lo, float hi) {
    u64 r; asm("mov.b64 %0, {%1, %2};" : "=l"(r) : "f"(lo), "f"(hi)); return r;
}
__device__ __forceinline__ u64 dup(float v) {
    u64 r; asm("mov.b64 %0, {%1, %1};" : "=l"(r) : "f"(v)); return r;
}
__device__ __forceinline__ void upk(u64 v, float& lo, float& hi) {
    asm("mov.b64 {%0, %1}, %2;" : "=f"(lo), "=f"(hi) : "l"(v));
}
__device__ __forceinline__ u64 ffma2(u64 a, u64 b, u64 c) {
    u64 d; asm("fma.rn.f32x2 %0, %1, %2, %3;" : "=l"(d) : "l"(a), "l"(b), "l"(c)); return d;
}
__device__ __forceinline__ u64 add2(u64 a, u64 b) {
    u64 d; asm("add.rn.f32x2 %0, %1, %2;" : "=l"(d) : "l"(a), "l"(b)); return d;
}
__device__ __forceinline__ u64 mul2(u64 a, u64 b) {
    u64 d; asm("mul.rn.f32x2 %0, %1, %2;" : "=l"(d) : "l"(a), "l"(b)); return d;
}
__device__ __forceinline__ u64 relu2(u64 v) {
    float lo, hi; upk(v, lo, hi);
    return pk(fmaxf(lo, 0.0f), fmaxf(hi, 0.0f));
}
// x = 0.5*logit: sigmoid(L) = 0.5*tanh(0.5L) + 0.5
__device__ __forceinline__ float sig_h(float x) {
    float t;
    asm("tanh.approx.f32 %0, %1;" : "=f"(t) : "f"(x));
    return fmaf(0.5f, t, 0.5f);
}

__global__ __launch_bounds__(NT, 4)
void dmh_kernel(const float* __restrict__ feats,     // [2, 8, 96, 160]
                const float* __restrict__ p1,        // [N, 169]
                const float* __restrict__ p2,        // [N, 169]
                const float* __restrict__ loc,       // [N, 2]
                const float* __restrict__ off,       // [N, 2]
                const int*   __restrict__ imi,       // [N]
                const int*   __restrict__ fpn,       // [N]
                float*       __restrict__ out)       // [2, N, 192, 320]
{
    extern __shared__ u64 smem_u64[];
    u64* sLp = smem_u64;                       // [TILE_PAIRS] packed half-logits
    u64* swp = smem_u64 + TILE_PAIRS;          // [SWPAIRS] weight pairs

    const int tid    = threadIdx.x;
    const int inst   = blockIdx.x;
    const int slab   = blockIdx.y;             // 0..5
    const int n_inst = gridDim.x;

    // ---- Repack: interleave head0/head1 weights into pairs ----
    if (tid < NP) {
        float w1 = p1[inst * NP + tid];
        float w2 = p2[inst * NP + tid];
        int d;
        if      (tid < 80)  { const int c = tid / 10; d = (tid - c * 10) * 8 + c; }        // l0wT
        else if (tid < 144) { const int i = tid - 80; d = 88 + (i / 8) * 10 + (i % 8); }   // l1w
        else if (tid < 152) { d = 88 + (tid - 144) * 10 + 9; w1 *= 0.5f; w2 *= 0.5f; }     // l2w
        else if (tid < 160) { d = 80 + (tid - 152); }                                      // l0b
        else if (tid < 168) { d = 88 + (tid - 160) * 10 + 8; }                             // l1b
        else                { d = 168; w1 *= 0.5f; w2 *= 0.5f; }                           // l2b
        swp[d] = pk(w1, w2);
    }

    const int   lvl     = fpn[inst];
    const float inv_soi = 1.0f / (64.0f * (float)(1 << lvl));
    const float lx0 = loc[2 * inst + 0];
    const float ly0 = loc[2 * inst + 1];
    const float lx1 = lx0 + off[2 * inst + 0] * 128.0f;
    const float ly1 = ly0 + off[2 * inst + 1] * 128.0f;
    const float* fb = feats + (size_t)imi[inst] * (8 * HW);
    const float dxs = -8.0f * inv_soi;
    __syncthreads();

    // ---------------- Phase 1: packed MLP, 2 px x 2 heads per iter ----------
    // slab s -> output rows [32s, 32s+32) -> input rows [16s-(s>0), 16s+16)
    const int ybase = 16 * slab - (slab ? 1 : 0);
    const int nrows = 16 + (slab ? 1 : 0);     // 16 or 17
    const int npx   = nrows * WW;

    #pragma unroll 1
    for (int p = 2 * tid; p < npx; p += 2 * NT) {
        const int rowl = p / WW;
        const int px   = p - rowl * WW;          // even
        const int y    = ybase + rowl;
        const int base = y * WW + px;

        // coordinate pairs {head0, head1}
        const float yc = (float)(y * 8 + 4);
        const float xc = (float)(px * 8 + 4);
        const u64 yp  = pk((ly0 - yc) * inv_soi, (ly1 - yc) * inv_soi);
        const u64 xpA = pk((lx0 - xc) * inv_soi, (lx1 - xc) * inv_soi);
        const u64 xpB = add2(xpA, dup(dxs));

        // features for the 2 pixels (8 x LDG.64)
        float2 f2[8];
        #pragma unroll
        for (int j = 0; j < 8; ++j)
            f2[j] = *reinterpret_cast<const float2*>(fb + j * HW + base);

        // layer-0 accumulators: bias pairs
        u64 a0[8], a1[8];
        {
            const ulonglong2* bp = reinterpret_cast<const ulonglong2*>(swp + 80);
            #pragma unroll
            for (int h = 0; h < 4; ++h) {
                const ulonglong2 b = bp[h];
                a0[2 * h] = b.x; a0[2 * h + 1] = b.y;
                a1[2 * h] = b.x; a1[2 * h + 1] = b.y;
            }
        }

        // layer 0, input-outer over transposed weights
        #define L0STEP(I, XA, XB)                                             \
        {                                                                     \
            const ulonglong2* Wp = reinterpret_cast<const ulonglong2*>(swp + (I) * 8); \
            const ulonglong2 wa = Wp[0], wb = Wp[1], wc = Wp[2], wd = Wp[3];  \
            a0[0] = ffma2(XA, wa.x, a0[0]);  a1[0] = ffma2(XB, wa.x, a1[0]);  \
            a0[1] = ffma2(XA, wa.y, a0[1]);  a1[1] = ffma2(XB, wa.y, a1[1]);  \
            a0[2] = ffma2(XA, wb.x, a0[2]);  a1[2] = ffma2(XB, wb.x, a1[2]);  \
            a0[3] = ffma2(XA, wb.y, a0[3]);  a1[3] = ffma2(XB, wb.y, a1[3]);  \
            a0[4] = ffma2(XA, wc.x, a0[4]);  a1[4] = ffma2(XB, wc.x, a1[4]);  \
            a0[5] = ffma2(XA, wc.y, a0[5]);  a1[5] = ffma2(XB, wc.y, a1[5]);  \
            a0[6] = ffma2(XA, wd.x, a0[6]);  a1[6] = ffma2(XB, wd.x, a1[6]);  \
            a0[7] = ffma2(XA, wd.y, a0[7]);  a1[7] = ffma2(XB, wd.y, a1[7]);  \
        }
        L0STEP(0, xpA, xpB)
        L0STEP(1, yp,  yp)
        #pragma unroll
        for (int j = 0; j < 8; ++j) {
            const u64 fd0 = dup(f2[j].x);
            const u64 fd1 = dup(f2[j].y);
            L0STEP(2 + j, fd0, fd1)
        }
        #undef L0STEP

        #pragma unroll
        for (int c = 0; c < 8; ++c) { a0[c] = relu2(a0[c]); a1[c] = relu2(a1[c]); }

        // layer 1 channel-outer ({bias,w2} packed), layer 2 streamed into o
        u64 o0 = swp[168], o1 = o0;
        #pragma unroll
        for (int c = 0; c < 8; ++c) {
            const ulonglong2* Wp = reinterpret_cast<const ulonglong2*>(swp + 88 + c * 10);
            const ulonglong2 wa = Wp[0], wb = Wp[1], wc = Wp[2], wd = Wp[3];
            const ulonglong2 bw = Wp[4];          // {bias, w2}
            u64 b0 = ffma2(a0[0], wa.x, bw.x);
            u64 b1 = ffma2(a1[0], wa.x, bw.x);
            b0 = ffma2(a0[1], wa.y, b0);  b1 = ffma2(a1[1], wa.y, b1);
            b0 = ffma2(a0[2], wb.x, b0);  b1 = ffma2(a1[2], wb.x, b1);
            b0 = ffma2(a0[3], wb.y, b0);  b1 = ffma2(a1[3], wb.y, b1);
            b0 = ffma2(a0[4], wc.x, b0);  b1 = ffma2(a1[4], wc.x, b1);
            b0 = ffma2(a0[5], wc.y, b0);  b1 = ffma2(a1[5], wc.y, b1);
            b0 = ffma2(a0[6], wd.x, b0);  b1 = ffma2(a1[6], wd.x, b1);
            b0 = ffma2(a0[7], wd.y, b0);  b1 = ffma2(a1[7], wd.y, b1);
            o0 = ffma2(relu2(b0), bw.y, o0);
            o1 = ffma2(relu2(b1), bw.y, o1);
        }

        sLp[rowl * WW + px]     = o0;    // packed {h0, h1} half-logits
        sLp[rowl * WW + px + 1] = o1;
    }
    __syncthreads();

    // ---------------- Phase 2: packed bilinear x2 + sigmoid ------------------
    // S_i = P[rA][i] + P[rB][i]  (rA==rB for odd rows -> S = 2P)
    //   col 4g: 0.25*(S_{cm1}+S_{c0})   4g+1: 0.5*S_{c0}
    //   4g+2:   0.25*(S_{c0}+S_{c1})    4g+3: 0.5*S_{c1}
    const u64 H = dup(0.5f);
    const u64 Q = dup(0.25f);
    float* ob0 = out + (size_t)inst * (192 * OW);
    float* ob1 = out + ((size_t)n_inst + inst) * (192 * OW);

    // 32 output rows x 80 quad-groups = 2560 items; 14 guarded iters
    #pragma unroll 1
    for (int it = 0; it < 14; ++it) {
        const int q = tid + it * NT;
        if (q >= 32 * 80) break;
        const int oyl = q / 80;                 // 0..31
        const int g   = q - oyl * 80;           // 0..79
        const int oy  = 32 * slab + oyl;

        const int r1  = oy >> 1;
        const int rA  = (oy & 1) ? r1 : ((r1 > 0) ? r1 - 1 : 0);
        const u64* RB = sLp + (r1 - ybase) * WW;
        const u64* RA = sLp + (rA - ybase) * WW;

        const int c0  = 2 * g;                  // even -> 16B aligned
        const int cm1 = (g > 0) ? c0 - 1 : c0;

        const ulonglong2 pb = *reinterpret_cast<const ulonglong2*>(RB + c0);
        const ulonglong2 pa = *reinterpret_cast<const ulonglong2*>(RA + c0);
        const u64 Sm = add2(RA[cm1], RB[cm1]);
        const u64 S0 = add2(pa.x, pb.x);
        const u64 S1 = add2(pa.y, pb.y);

        const u64 e0 = mul2(add2(Sm, S0), Q);
        const u64 e1 = mul2(S0, H);
        const u64 e2 = mul2(add2(S0, S1), Q);
        const u64 e3 = mul2(S1, H);

        float a0, b0, a1, b1, a2, b2, a3, b3;
        upk(e0, a0, b0); upk(e1, a1, b1); upk(e2, a2, b2); upk(e3, a3, b3);

        float4 v0, v1;
        v0.x = sig_h(a0); v0.y = sig_h(a1); v0.z = sig_h(a2); v0.w = sig_h(a3);
        v1.x = sig_h(b0); v1.y = sig_h(b1); v1.z = sig_h(b2); v1.w = sig_h(b3);

        const int o = oy * OW + 4 * g;
        *reinterpret_cast<float4*>(ob0 + o) = v0;
        *reinterpret_cast<float4*>(ob1 + o) = v1;
    }
}

extern "C" void kernel_launch(void* const* d_in, const int* in_sizes, int n_in,
                              void* d_out, int out_size)
{
    const float* feats = (const float*)d_in[0];
    const float* p1    = (const float*)d_in[1];
    const float* p2    = (const float*)d_in[2];
    const float* loc   = (const float*)d_in[3];
    const float* off   = (const float*)d_in[4];
    const int*   imi   = (const int*)  d_in[5];
    const int*   fpn   = (const int*)  d_in[6];
    float* out = (float*)d_out;

    const int n_inst = in_sizes[5];   // 200

    static bool attr_set = false;
    if (!attr_set) {
        cudaFuncSetAttribute(dmh_kernel,
                             cudaFuncAttributeMaxDynamicSharedMemorySize,
                             (int)SMEM_BYTES);
        attr_set = true;
    }

    dim3 grid(n_inst, 6);             // 1200 half-size blocks ~ 2 waves @4 CTA/SM
    dmh_kernel<<<grid, NT, SMEM_BYTES>>>(feats, p1, p2, loc, off, imi, fpn, out);
}